// round 4
// baseline (speedup 1.0000x reference)
#include <cuda_runtime.h>
#include <cstdint>

// Problem constants (fixed by reference setup_inputs)
#define NIMG 8          // batch
#define HW   512        // image H=W
#define BLK  32         // block size
#define NB   16         // blocks per dim
#define NP   256        // regions
#define KPSF 64         // psf size
#define QD   65         // folded kernel dim
#define QSZ  (QD*QD)    // 4225
#define OUTD 127        // per-region output dim
#define SN   1024       // sensor dim

// Folded kernel: Q[p][u+1][v+1] = sum_{dy,dx in {0,1}} psf[p][u+dy][v+dx] (valid taps only)
__device__ float g_Q[NP * QSZ];

__global__ void build_q_kernel(const float* __restrict__ psf) {
    int p = blockIdx.x;
    const float* w = psf + (size_t)p * KPSF * KPSF;
    for (int i = threadIdx.x; i < QSZ; i += blockDim.x) {
        int r = i / QD, c = i % QD;       // r = u+1, c = v+1
        float s = 0.0f;
        #pragma unroll
        for (int dy = 0; dy < 2; ++dy) {
            int a = r - 1 + dy;
            if (a < 0 || a >= KPSF) continue;
            #pragma unroll
            for (int dx = 0; dx < 2; ++dx) {
                int b = c - 1 + dx;
                if (b < 0 || b >= KPSF) continue;
                s += w[a * KPSF + b];
            }
        }
        g_Q[p * QSZ + i] = s;
    }
}

// One CTA per (region p, 32x32 output tile). 8 warps; each warp owns 4
// consecutive output rows; each lane owns one x column. Accumulates all 8
// batch images as f32x2 pairs via fma.rn.f32x2 (2x fp32 throughput).
__global__ __launch_bounds__(256) void conv_scatter_kernel(
    const float* __restrict__ imgs,
    const float* __restrict__ xc,
    const float* __restrict__ yc,
    float* __restrict__ out)
{
    extern __shared__ float smem[];
    float* sBlk = smem;                 // [32*32][8]  (n innermost, 32B slots)
    float* sQ   = smem + BLK * BLK * NIMG;  // [65*65]

    const int p  = blockIdx.y;
    const int bh = p & 15, bw = p >> 4;
    const int tid = threadIdx.x;

    // Stage the 32x32 block of every image (n innermost for vector LDS later)
    const float* ibase = imgs + (size_t)(bh * BLK) * HW + bw * BLK;
    for (int i = tid; i < BLK * BLK; i += 256) {
        int by = i >> 5, bx = i & 31;
        const float* g = ibase + by * HW + bx;
        #pragma unroll
        for (int n = 0; n < NIMG; ++n)
            sBlk[i * NIMG + n] = g[(size_t)n * HW * HW];
    }
    // Stage folded kernel
    const float* gq = g_Q + p * QSZ;
    for (int i = tid; i < QSZ; i += 256) sQ[i] = gq[i];
    __syncthreads();

    const int tile = blockIdx.x;
    const int y0 = (tile >> 2) * 32, x0 = (tile & 3) * 32;
    const int warp = tid >> 5, lane = tid & 31;
    const int yb = y0 + warp * 4;       // this thread's 4 rows: yb..yb+3 (yb even)
    const int x  = x0 + lane;

    // Exact per-warp by range: 2by >= yb-64 and 2by <= yb+3
    const int by_lo = max(0, yb / 2 - 32);
    const int by_hi = min(31, yb / 2 + 1);
    // CTA-uniform bx range over x in [x0, x0+31]
    const int bx_lo = max(0, x0 / 2 - 32);
    const int bx_hi = min(31, (x0 + 31) / 2);

    unsigned long long acc[4][4];       // [row k][image pair j] packed f32x2
    #pragma unroll
    for (int k = 0; k < 4; ++k)
        #pragma unroll
        for (int j = 0; j < 4; ++j) acc[k][j] = 0ULL;

    for (int by = by_lo; by <= by_hi; ++by) {
        const int qr0 = 2 * by + 64 - yb;     // Q row index for k=0 (= u0+1)
        const float* blkRow = sBlk + ((by << 5) * NIMG);
        for (int bx = bx_lo; bx <= bx_hi; ++bx) {
            const int qc = 2 * bx + 64 - x;   // Q col index (= v+1)
            const bool cok = ((unsigned)qc <= 64u);
            const ulonglong2* bp =
                (const ulonglong2*)(blkRow + bx * NIMG);
            const ulonglong2 b01 = bp[0];     // images {0,1},{2,3}
            const ulonglong2 b23 = bp[1];     // images {4,5},{6,7}
            const int qidx0 = qr0 * QD + qc;
            #pragma unroll
            for (int k = 0; k < 4; ++k) {
                const int qr = qr0 - k;
                const float q =
                    (cok && (unsigned)qr <= 64u) ? sQ[qidx0 - k * QD] : 0.0f;
                unsigned long long q2;
                asm("mov.b64 %0, {%1, %1};" : "=l"(q2) : "f"(q));
                asm("fma.rn.f32x2 %0, %1, %2, %0;"
                    : "+l"(acc[k][0]) : "l"(b01.x), "l"(q2));
                asm("fma.rn.f32x2 %0, %1, %2, %0;"
                    : "+l"(acc[k][1]) : "l"(b01.y), "l"(q2));
                asm("fma.rn.f32x2 %0, %1, %2, %0;"
                    : "+l"(acc[k][2]) : "l"(b23.x), "l"(q2));
                asm("fma.rn.f32x2 %0, %1, %2, %0;"
                    : "+l"(acc[k][3]) : "l"(b23.y), "l"(q2));
            }
        }
    }

    // Scatter-add this tile into the sensor (footprints always in-bounds)
    const int ic = 512 + __float2int_rn(xc[p] * 1e6f);
    const int jc = 512 + __float2int_rn(yc[p] * 1e6f);
    const int I0 = ic - 63, J0 = jc - 63;
    if (x < OUTD) {
        const int J = J0 + x;
        #pragma unroll
        for (int k = 0; k < 4; ++k) {
            const int y = yb + k;
            if (y >= OUTD) break;
            float* o = out + (size_t)(I0 + y) * SN + J;
            #pragma unroll
            for (int j = 0; j < 4; ++j) {
                const float lo = __uint_as_float((unsigned)(acc[k][j]));
                const float hi = __uint_as_float((unsigned)(acc[k][j] >> 32));
                atomicAdd(o + (size_t)(2 * j)     * (SN * SN), lo);
                atomicAdd(o + (size_t)(2 * j + 1) * (SN * SN), hi);
            }
        }
    }
}

extern "C" void kernel_launch(void* const* d_in, const int* in_sizes, int n_in,
                              void* d_out, int out_size) {
    const float* imgs = (const float*)d_in[0];
    const float* psf  = (const float*)d_in[1];
    const float* xc   = (const float*)d_in[4];
    const float* yc   = (const float*)d_in[5];
    float* out = (float*)d_out;

    // Zero the sensor (capturable memset node)
    cudaMemsetAsync(out, 0, (size_t)out_size * sizeof(float), 0);

    // Build folded 65x65 kernels from the 64x64 PSFs
    build_q_kernel<<<NP, 256>>>(psf);

    // Main conv + scatter
    const int smemBytes = (BLK * BLK * NIMG + QSZ) * (int)sizeof(float); // 49668
    cudaFuncSetAttribute(conv_scatter_kernel,
                         cudaFuncAttributeMaxDynamicSharedMemorySize, smemBytes);
    dim3 grid(16, NP);
    conv_scatter_kernel<<<grid, 256, smemBytes>>>(imgs, xc, yc, out);
}

// round 8
// speedup vs baseline: 1.2822x; 1.2822x over previous
#include <cuda_runtime.h>
#include <cstdint>

// Problem constants (fixed by reference setup_inputs)
#define NIMG 8          // batch
#define HW   512        // image H=W
#define BLK  32         // block size
#define NP   256        // regions
#define KPSF 64         // psf size
#define QD   65         // folded kernel dim
#define QSZ  (QD*QD)    // 4225
#define OUTD 127        // per-region output dim
#define SN   1024       // sensor dim

#define QCOLS 80        // padded per-CTA Q column window (max span 78)
#define QROWS 65

// Folded kernel: Q[p][u+1][v+1] = sum_{dy,dx in {0,1}} psf[p][u+dy][v+dx] (valid taps)
__device__ float g_Q[NP * QSZ];

__global__ void build_q_kernel(const float* __restrict__ psf) {
    int p = blockIdx.x;
    const float* w = psf + (size_t)p * KPSF * KPSF;
    for (int i = threadIdx.x; i < QSZ; i += blockDim.x) {
        int r = i / QD, c = i % QD;       // r = u+1, c = v+1
        float s = 0.0f;
        #pragma unroll
        for (int dy = 0; dy < 2; ++dy) {
            int a = r - 1 + dy;
            if (a < 0 || a >= KPSF) continue;
            #pragma unroll
            for (int dx = 0; dx < 2; ++dx) {
                int b = c - 1 + dx;
                if (b < 0 || b >= KPSF) continue;
                s += w[a * KPSF + b];
            }
        }
        g_Q[p * QSZ + i] = s;
    }
}

#define FMA2(a, b, q) \
    asm("fma.rn.f32x2 %0, %1, %2, %0;" : "+l"(a) : "l"(b), "l"(q))

// One CTA per (region p, 64y x 16x output tile). 8 warps; warp w owns rows
// [y0+8w, y0+8w+8); lane = (ky, xi): thread covers 4 rows yb..yb+3 at column x.
// Q staged in smem as zero-padded DUPLICATED f32x2 pairs -> inner loop is pure
// LDS + fma.rn.f32x2, no predication, no splat MOVs.
__global__ __launch_bounds__(256, 3) void conv_scatter_kernel(
    const float* __restrict__ imgs,
    const float* __restrict__ xc,
    const float* __restrict__ yc,
    float* __restrict__ out)
{
    extern __shared__ float smem[];
    float* sBlk = smem;                                   // [32*32][8] n innermost
    unsigned long long* sQd =
        (unsigned long long*)(smem + BLK * BLK * NIMG);   // [65][80] dup pairs

    const int p  = blockIdx.y;
    const int bh = p & 15, bw = p >> 4;
    const int tid = threadIdx.x;

    const int tile = blockIdx.x;            // 0..15
    const int x0 = (tile & 7) * 16;
    const int y0 = (tile >> 3) * 64;

    // CTA-uniform bx range over x in [x0, x0+15]
    const int bx_lo = max(0, x0 / 2 - 32);
    const int bx_hi = min(31, (x0 + 15) / 2);
    const int qcbase = 2 * bx_lo + 64 - (x0 + 15);   // min qc over executed range

    // Stage the 32x32 block of every image (n innermost, 32B slots)
    const float* ibase = imgs + (size_t)(bh * BLK) * HW + bw * BLK;
    for (int i = tid; i < BLK * BLK; i += 256) {
        int by = i >> 5, bx = i & 31;
        const float* g = ibase + by * HW + bx;
        #pragma unroll
        for (int n = 0; n < NIMG; ++n)
            sBlk[i * NIMG + n] = g[(size_t)n * HW * HW];
    }
    // Stage zero-padded duplicated Q window: sQd[qr][c], qc = qcbase + c
    const float* gq = g_Q + p * QSZ;
    for (int i = tid; i < QROWS * QCOLS; i += 256) {
        int qr = i / QCOLS, c = i - qr * QCOLS;
        int qc = qcbase + c;
        float v = ((unsigned)qc <= 64u) ? gq[qr * QD + qc] : 0.0f;
        unsigned u = __float_as_uint(v);
        sQd[i] = ((unsigned long long)u << 32) | u;
    }
    __syncthreads();

    const int warp = tid >> 5, lane = tid & 31;
    const int ky = lane >> 4, xi = lane & 15;
    const int yb = y0 + warp * 8 + ky * 4;  // this thread's rows yb..yb+3
    const int x  = x0 + xi;
    const int col0 = 15 - xi;               // smem Q col at bx = bx_lo

    // by ranges: full and interior (all 4 k valid: qr0 in [4,64])
    const int blo = max(0, (yb >> 1) - 32);
    const int bhi = min(31, (yb >> 1) + 1);
    int ilo = max(blo, (yb - 60) >> 1);
    int ihi = min(bhi, yb >> 1);
    if (ilo > ihi) { ilo = bhi + 1; ihi = bhi; }   // empty interior

    unsigned long long acc[4][4];           // [row k][image pair j]
    #pragma unroll
    for (int k = 0; k < 4; ++k)
        #pragma unroll
        for (int j = 0; j < 4; ++j) acc[k][j] = 0ULL;

    // ---- boundary (low): qr0 in {0,2}; per-k guarded ----
    for (int by = blo; by < ilo; ++by) {
        const int qr0 = 2 * by + 64 - yb;
        const float* bp = sBlk + (size_t)(by * 32 + bx_lo) * NIMG;
        const unsigned long long* qb = sQd + col0;
        int coff = 0;
        for (int bx = bx_lo; bx <= bx_hi; ++bx) {
            const ulonglong2 b01 = *(const ulonglong2*)bp;
            const ulonglong2 b23 = *(const ulonglong2*)(bp + 4);
            #pragma unroll
            for (int k = 0; k < 4; ++k) {
                const int qr = qr0 - k;
                unsigned long long q = 0ULL;
                if ((unsigned)qr <= 64u) q = qb[qr * QCOLS + coff];
                FMA2(acc[k][0], b01.x, q);
                FMA2(acc[k][1], b01.y, q);
                FMA2(acc[k][2], b23.x, q);
                FMA2(acc[k][3], b23.y, q);
            }
            bp += NIMG; coff += 2;
        }
    }

    // ---- interior: no predication anywhere ----
    for (int by = ilo; by <= ihi; ++by) {
        const int qr0 = 2 * by + 64 - yb;                 // in [4,64]
        const unsigned long long* qp = sQd + (qr0 - 3) * QCOLS + col0;
        const float* bp = sBlk + (size_t)(by * 32 + bx_lo) * NIMG;
        #pragma unroll 2
        for (int bx = bx_lo; bx <= bx_hi; ++bx) {
            const ulonglong2 b01 = *(const ulonglong2*)bp;
            const ulonglong2 b23 = *(const ulonglong2*)(bp + 4);
            const unsigned long long q3 = qp[0];          // row qr0-3 -> k=3
            const unsigned long long q2 = qp[QCOLS];      // k=2
            const unsigned long long q1 = qp[2 * QCOLS];  // k=1
            const unsigned long long q0 = qp[3 * QCOLS];  // k=0
            FMA2(acc[0][0], b01.x, q0);
            FMA2(acc[0][1], b01.y, q0);
            FMA2(acc[0][2], b23.x, q0);
            FMA2(acc[0][3], b23.y, q0);
            FMA2(acc[1][0], b01.x, q1);
            FMA2(acc[1][1], b01.y, q1);
            FMA2(acc[1][2], b23.x, q1);
            FMA2(acc[1][3], b23.y, q1);
            FMA2(acc[2][0], b01.x, q2);
            FMA2(acc[2][1], b01.y, q2);
            FMA2(acc[2][2], b23.x, q2);
            FMA2(acc[2][3], b23.y, q2);
            FMA2(acc[3][0], b01.x, q3);
            FMA2(acc[3][1], b01.y, q3);
            FMA2(acc[3][2], b23.x, q3);
            FMA2(acc[3][3], b23.y, q3);
            bp += NIMG; qp += 2;
        }
    }

    // ---- boundary (high): qr0 = 66; per-k guarded ----
    for (int by = ihi + 1; by <= bhi; ++by) {
        const int qr0 = 2 * by + 64 - yb;
        const float* bp = sBlk + (size_t)(by * 32 + bx_lo) * NIMG;
        const unsigned long long* qb = sQd + col0;
        int coff = 0;
        for (int bx = bx_lo; bx <= bx_hi; ++bx) {
            const ulonglong2 b01 = *(const ulonglong2*)bp;
            const ulonglong2 b23 = *(const ulonglong2*)(bp + 4);
            #pragma unroll
            for (int k = 0; k < 4; ++k) {
                const int qr = qr0 - k;
                unsigned long long q = 0ULL;
                if ((unsigned)qr <= 64u) q = qb[qr * QCOLS + coff];
                FMA2(acc[k][0], b01.x, q);
                FMA2(acc[k][1], b01.y, q);
                FMA2(acc[k][2], b23.x, q);
                FMA2(acc[k][3], b23.y, q);
            }
            bp += NIMG; coff += 2;
        }
    }

    // Scatter-add into the sensor (footprints always in-bounds)
    const int ic = 512 + __float2int_rn(xc[p] * 1e6f);
    const int jc = 512 + __float2int_rn(yc[p] * 1e6f);
    const int I0 = ic - 63, J0 = jc - 63;
    if (x < OUTD) {
        const int J = J0 + x;
        #pragma unroll
        for (int k = 0; k < 4; ++k) {
            const int y = yb + k;
            if (y < OUTD) {
                float* o = out + (size_t)(I0 + y) * SN + J;
                #pragma unroll
                for (int j = 0; j < 4; ++j) {
                    const float lo = __uint_as_float((unsigned)(acc[k][j]));
                    const float hi = __uint_as_float((unsigned)(acc[k][j] >> 32));
                    atomicAdd(o + (size_t)(2 * j)     * (SN * SN), lo);
                    atomicAdd(o + (size_t)(2 * j + 1) * (SN * SN), hi);
                }
            }
        }
    }
}

extern "C" void kernel_launch(void* const* d_in, const int* in_sizes, int n_in,
                              void* d_out, int out_size) {
    const float* imgs = (const float*)d_in[0];
    const float* psf  = (const float*)d_in[1];
    const float* xc   = (const float*)d_in[4];
    const float* yc   = (const float*)d_in[5];
    float* out = (float*)d_out;

    // Zero the sensor (capturable memset node)
    cudaMemsetAsync(out, 0, (size_t)out_size * sizeof(float), 0);

    // Build folded 65x65 kernels from the 64x64 PSFs
    build_q_kernel<<<NP, 256>>>(psf);

    // Main conv + scatter: 16 tiles (8 x-tiles x 2 y-tiles) per region
    const int smemBytes = BLK * BLK * NIMG * (int)sizeof(float)
                        + QROWS * QCOLS * (int)sizeof(unsigned long long); // 74368
    cudaFuncSetAttribute(conv_scatter_kernel,
                         cudaFuncAttributeMaxDynamicSharedMemorySize, smemBytes);
    dim3 grid(16, NP);
    conv_scatter_kernel<<<grid, 256, smemBytes>>>(imgs, xc, yc, out);
}

// round 10
// speedup vs baseline: 1.3363x; 1.0422x over previous
#include <cuda_runtime.h>
#include <cstdint>

// Problem constants (fixed by reference setup_inputs)
#define NIMG 8          // batch
#define HW   512        // image H=W
#define BLK  32         // block size
#define NP   256        // regions
#define KPSF 64         // psf size
#define QD   65         // folded kernel dim
#define QSZ  (QD*QD)    // 4225
#define OUTD 127        // per-region output dim
#define SN   1024       // sensor dim

#define QCOLS 78        // per-CTA Q column window (max needed span = 78)
#define QCLEN 66        // padded column length in pairs (row qr at slot qr+1)
                        // stride 66 pairs = 132 words == 4 banks/lane -> conflict-free

// Folded kernel: Q[p][u+1][v+1] = sum_{dy,dx in {0,1}} psf[p][u+dy][v+dx] (valid taps)
__device__ float g_Q[NP * QSZ];

__global__ void build_q_kernel(const float* __restrict__ psf) {
    int p = blockIdx.x;
    const float* w = psf + (size_t)p * KPSF * KPSF;
    for (int i = threadIdx.x; i < QSZ; i += blockDim.x) {
        int r = i / QD, c = i % QD;       // r = u+1, c = v+1
        float s = 0.0f;
        #pragma unroll
        for (int dy = 0; dy < 2; ++dy) {
            int a = r - 1 + dy;
            if (a < 0 || a >= KPSF) continue;
            #pragma unroll
            for (int dx = 0; dx < 2; ++dx) {
                int b = c - 1 + dx;
                if (b < 0 || b >= KPSF) continue;
                s += w[a * KPSF + b];
            }
        }
        g_Q[p * QSZ + i] = s;
    }
}

#define FMA2(a, b, q) \
    asm("fma.rn.f32x2 %0, %1, %2, %0;" : "+l"(a) : "l"(b), "l"(q))

#define FMA16(B01, B23, Q32, Q10)            \
    do {                                     \
        FMA2(acc[0][0], (B01).x, (Q10).y);   \
        FMA2(acc[0][1], (B01).y, (Q10).y);   \
        FMA2(acc[0][2], (B23).x, (Q10).y);   \
        FMA2(acc[0][3], (B23).y, (Q10).y);   \
        FMA2(acc[1][0], (B01).x, (Q10).x);   \
        FMA2(acc[1][1], (B01).y, (Q10).x);   \
        FMA2(acc[1][2], (B23).x, (Q10).x);   \
        FMA2(acc[1][3], (B23).y, (Q10).x);   \
        FMA2(acc[2][0], (B01).x, (Q32).y);   \
        FMA2(acc[2][1], (B01).y, (Q32).y);   \
        FMA2(acc[2][2], (B23).x, (Q32).y);   \
        FMA2(acc[2][3], (B23).y, (Q32).y);   \
        FMA2(acc[3][0], (B01).x, (Q32).x);   \
        FMA2(acc[3][1], (B01).y, (Q32).x);   \
        FMA2(acc[3][2], (B23).x, (Q32).x);   \
        FMA2(acc[3][3], (B23).y, (Q32).x);   \
    } while (0)

// One CTA per (region p, 64y x 16x output tile). 8 warps; warp w owns rows
// [y0+8w, y0+8w+8); lane = (ky, xi): thread covers 4 rows yb..yb+3 at column x.
// Q staged in smem COLUMN-major as zero-padded duplicated f32x2 pairs:
// pair for (row qr, col c) at sQd[c*QCLEN + qr + 1]. The 4 k-rows of one
// iteration are contiguous and 16B aligned -> 2x LDS.128. Interior loop is
// software-pipelined (prefetch next bx) to hide LDS latency.
__global__ __launch_bounds__(256, 3) void conv_scatter_kernel(
    const float* __restrict__ imgs,
    const float* __restrict__ xc,
    const float* __restrict__ yc,
    float* __restrict__ out)
{
    extern __shared__ float smem[];
    float* sBlk = smem;                                   // [32*32][8] n innermost
    unsigned long long* sQd =
        (unsigned long long*)(smem + BLK * BLK * NIMG);   // [78 cols][66 pairs]

    const int p  = blockIdx.y;
    const int bh = p & 15, bw = p >> 4;
    const int tid = threadIdx.x;

    const int tile = blockIdx.x;            // 0..15
    const int x0 = (tile & 7) * 16;
    const int y0 = (tile >> 3) * 64;

    // CTA-uniform bx range over x in [x0, x0+15]
    const int bx_lo = max(0, x0 / 2 - 32);
    const int bx_hi = min(31, (x0 + 15) / 2);
    const int qcbase = 2 * bx_lo + 64 - (x0 + 15);   // min qc over executed range

    // Stage the 32x32 block of every image (n innermost, 32B slots)
    const float* ibase = imgs + (size_t)(bh * BLK) * HW + bw * BLK;
    for (int i = tid; i < BLK * BLK; i += 256) {
        int by = i >> 5, bx = i & 31;
        const float* g = ibase + by * HW + bx;
        #pragma unroll
        for (int n = 0; n < NIMG; ++n)
            sBlk[i * NIMG + n] = g[(size_t)n * HW * HW];
    }
    // Stage zero-padded duplicated Q, column-major with +1 row shift
    const float* gq = g_Q + p * QSZ;
    for (int i = tid; i < QCOLS * QCLEN; i += 256) {
        int c = i / QCLEN, s = i - c * QCLEN;   // s = qr + 1
        int qr = s - 1, qc = qcbase + c;
        float v = (qr >= 0 && qr <= 64 && (unsigned)qc <= 64u)
                      ? gq[qr * QD + qc] : 0.0f;
        unsigned u = __float_as_uint(v);
        sQd[i] = ((unsigned long long)u << 32) | u;
    }
    __syncthreads();

    const int warp = tid >> 5, lane = tid & 31;
    const int ky = lane >> 4, xi = lane & 15;
    const int yb = y0 + warp * 8 + ky * 4;  // this thread's rows yb..yb+3 (yb even)
    const int x  = x0 + xi;
    const int col0 = 15 - xi;               // smem Q col at bx = bx_lo

    // by ranges: full and interior (all 4 k valid: qr0 in [4,64])
    const int blo = max(0, (yb >> 1) - 32);
    const int bhi = min(31, (yb >> 1) + 1);
    int ilo = max(blo, (yb - 60) >> 1);
    int ihi = min(bhi, yb >> 1);
    if (ilo > ihi) { ilo = bhi + 1; ihi = bhi; }   // empty interior

    unsigned long long acc[4][4];           // [row k][image pair j]
    #pragma unroll
    for (int k = 0; k < 4; ++k)
        #pragma unroll
        for (int j = 0; j < 4; ++j) acc[k][j] = 0ULL;

    // ---- boundary (low): qr0 in {0,2}; per-k guarded ----
    for (int by = blo; by < ilo; ++by) {
        const int qr0 = 2 * by + 64 - yb;
        const float* bp = sBlk + (size_t)(by * 32 + bx_lo) * NIMG;
        int c = col0;
        for (int bx = bx_lo; bx <= bx_hi; ++bx) {
            const ulonglong2 b01 = *(const ulonglong2*)bp;
            const ulonglong2 b23 = *(const ulonglong2*)(bp + 4);
            #pragma unroll
            for (int k = 0; k < 4; ++k) {
                const int qr = qr0 - k;
                unsigned long long q = 0ULL;
                if ((unsigned)qr <= 64u) q = sQd[c * QCLEN + qr + 1];
                FMA2(acc[k][0], b01.x, q);
                FMA2(acc[k][1], b01.y, q);
                FMA2(acc[k][2], b23.x, q);
                FMA2(acc[k][3], b23.y, q);
            }
            bp += NIMG; c += 2;
        }
    }

    // ---- interior: no predication; software-pipelined ----
    for (int by = ilo; by <= ihi; ++by) {
        const int qr0 = 2 * by + 64 - yb;                 // even, in [4,64]
        // pair slot of row qr0-3 = col0*QCLEN + (qr0-3) + 1 -> even => 16B aligned
        const unsigned long long* qp = sQd + col0 * QCLEN + (qr0 - 2);
        const float* bp = sBlk + (size_t)(by * 32 + bx_lo) * NIMG;

        ulonglong2 b01 = *(const ulonglong2*)bp;
        ulonglong2 b23 = *(const ulonglong2*)(bp + 4);
        ulonglong2 q32 = *(const ulonglong2*)qp;          // {q(k=3), q(k=2)}
        ulonglong2 q10 = *(const ulonglong2*)(qp + 2);    // {q(k=1), q(k=0)}

        #pragma unroll 2
        for (int bx = bx_lo; bx < bx_hi; ++bx) {
            bp += NIMG; qp += 2 * QCLEN;
            const ulonglong2 nb01 = *(const ulonglong2*)bp;
            const ulonglong2 nb23 = *(const ulonglong2*)(bp + 4);
            const ulonglong2 nq32 = *(const ulonglong2*)qp;
            const ulonglong2 nq10 = *(const ulonglong2*)(qp + 2);
            FMA16(b01, b23, q32, q10);
            b01 = nb01; b23 = nb23; q32 = nq32; q10 = nq10;
        }
        FMA16(b01, b23, q32, q10);
    }

    // ---- boundary (high): qr0 = 66; per-k guarded ----
    for (int by = ihi + 1; by <= bhi; ++by) {
        const int qr0 = 2 * by + 64 - yb;
        const float* bp = sBlk + (size_t)(by * 32 + bx_lo) * NIMG;
        int c = col0;
        for (int bx = bx_lo; bx <= bx_hi; ++bx) {
            const ulonglong2 b01 = *(const ulonglong2*)bp;
            const ulonglong2 b23 = *(const ulonglong2*)(bp + 4);
            #pragma unroll
            for (int k = 0; k < 4; ++k) {
                const int qr = qr0 - k;
                unsigned long long q = 0ULL;
                if ((unsigned)qr <= 64u) q = sQd[c * QCLEN + qr + 1];
                FMA2(acc[k][0], b01.x, q);
                FMA2(acc[k][1], b01.y, q);
                FMA2(acc[k][2], b23.x, q);
                FMA2(acc[k][3], b23.y, q);
            }
            bp += NIMG; c += 2;
        }
    }

    // Scatter-add into the sensor (footprints always in-bounds)
    const int ic = 512 + __float2int_rn(xc[p] * 1e6f);
    const int jc = 512 + __float2int_rn(yc[p] * 1e6f);
    const int I0 = ic - 63, J0 = jc - 63;
    if (x < OUTD) {
        const int J = J0 + x;
        #pragma unroll
        for (int k = 0; k < 4; ++k) {
            const int y = yb + k;
            if (y < OUTD) {
                float* o = out + (size_t)(I0 + y) * SN + J;
                #pragma unroll
                for (int j = 0; j < 4; ++j) {
                    const float lo = __uint_as_float((unsigned)(acc[k][j]));
                    const float hi = __uint_as_float((unsigned)(acc[k][j] >> 32));
                    atomicAdd(o + (size_t)(2 * j)     * (SN * SN), lo);
                    atomicAdd(o + (size_t)(2 * j + 1) * (SN * SN), hi);
                }
            }
        }
    }
}

extern "C" void kernel_launch(void* const* d_in, const int* in_sizes, int n_in,
                              void* d_out, int out_size) {
    const float* imgs = (const float*)d_in[0];
    const float* psf  = (const float*)d_in[1];
    const float* xc   = (const float*)d_in[4];
    const float* yc   = (const float*)d_in[5];
    float* out = (float*)d_out;

    // Zero the sensor (capturable memset node)
    cudaMemsetAsync(out, 0, (size_t)out_size * sizeof(float), 0);

    // Build folded 65x65 kernels from the 64x64 PSFs
    build_q_kernel<<<NP, 256>>>(psf);

    // Main conv + scatter: 16 tiles (8 x-tiles x 2 y-tiles) per region
    const int smemBytes = BLK * BLK * NIMG * (int)sizeof(float)
                        + QCOLS * QCLEN * (int)sizeof(unsigned long long); // 73952
    cudaFuncSetAttribute(conv_scatter_kernel,
                         cudaFuncAttributeMaxDynamicSharedMemorySize, smemBytes);
    cudaFuncSetAttribute(conv_scatter_kernel,
                         cudaFuncAttributePreferredSharedMemoryCarveout, 100);
    dim3 grid(16, NP);
    conv_scatter_kernel<<<grid, 256, smemBytes>>>(imgs, xc, yc, out);
}